// round 14
// baseline (speedup 1.0000x reference)
#include <cuda_runtime.h>
#include <cuda_fp16.h>

// Problem constants
#define B  2
#define C  256
#define H  200
#define W  336
#define R  1000
#define OH 14
#define OW 14
#define HW (H * W)           // 67200
#define SCALE 0.25f

#define TPB 448
#define TB_PER_BATCH 2400    // 600 pos-tiles (112) x 4 ch-groups (64)
#define GB_TOTAL (R * 7)     // 7000
#define ILV 5900             // interleave window: 2400 T1 + 3500 G
#define GRID_TOTAL (1 + TB_PER_BATCH + ILV + 3500)   // 11801

// NHWC features in fp16: 2*67200*256*2B = 68.8 MB
__device__ static __half g_feat[(size_t)B * HW * C];
// g_sync[0..1]: per-batch transpose counters; g_sync[2]: sort-done flag
__device__ static int g_sync[4];
__device__ static int g_sorted[R];

__global__ void init_ctr_kernel() {
    if (threadIdx.x < 4) g_sync[threadIdx.x] = 0;
}

#define TSTR 68   // transpose tile row stride (words)
#define RW   132  // gather staging row stride (words)

__device__ __forceinline__ void do_transpose(const float* __restrict__ feats,
                                             int batch, int tb, int t, float* tileT) {
    const int cgr = tb / 600;            // channel group 0..3
    const int pt  = tb - cgr * 600;      // position tile 0..599
    const int p0  = pt * 112;
    const int c0  = cgr * 64;
    const float* s = feats + (size_t)batch * C * HW;
    __half*      d = g_feat + (size_t)batch * HW * C;

    {
        const int px = t % 28;             // position quad
        const int cy = t / 28;             // channel quad 0..15
        const float* rb = s + (size_t)(c0 + cy * 4) * HW + p0 + px * 4;
        const float4 v0 = __ldcs((const float4*)(rb));
        const float4 v1 = __ldcs((const float4*)(rb + HW));
        const float4 v2 = __ldcs((const float4*)(rb + 2 * (size_t)HW));
        const float4 v3 = __ldcs((const float4*)(rb + 3 * (size_t)HW));

        float* wb = &tileT[(4 * px) * TSTR + 4 * ((cy ^ px) & 15)];
        *(float4*)(wb + 0 * TSTR) = make_float4(v0.x, v1.x, v2.x, v3.x);
        *(float4*)(wb + 1 * TSTR) = make_float4(v0.y, v1.y, v2.y, v3.y);
        *(float4*)(wb + 2 * TSTR) = make_float4(v0.z, v1.z, v2.z, v3.z);
        *(float4*)(wb + 3 * TSTR) = make_float4(v0.w, v1.w, v2.w, v3.w);
    }
    __syncthreads();
    {
        const int c4 = t % 16;
        const int pr = t / 16;             // 0..27
        #pragma unroll
        for (int k = 0; k < 4; k++) {
            const int p = pr + 28 * k;     // 0..111
            const float4 w = *(const float4*)&tileT[p * TSTR + 4 * ((c4 ^ (p >> 2)) & 15)];
            const __half2 h0 = __floats2half2_rn(w.x, w.y);
            const __half2 h1 = __floats2half2_rn(w.z, w.w);
            uint2 u;
            u.x = *reinterpret_cast<const unsigned int*>(&h0);
            u.y = *reinterpret_cast<const unsigned int*>(&h1);
            __stcg(reinterpret_cast<uint2*>(d + (size_t)(p0 + p) * C + c0 + c4 * 4), u);
        }
    }
    __threadfence();
    __syncthreads();
    if (t == 0) atomicAdd(&g_sync[batch], 1);
}

__global__ __launch_bounds__(TPB, 4) void fused_kernel(
    const float* __restrict__ feats, const float* __restrict__ rois,
    float* __restrict__ out)
{
    __shared__ __align__(16) unsigned char smem_raw[112 * TSTR * 4];  // 30464 B
    const int bid = blockIdx.x;
    const int t   = threadIdx.x;

    if (bid == 0) {
        // ---------------- sort role: ROIs grouped batch-0-first ----------------
        __shared__ int cnt[2], cur[2], base[2];
        if (t < 2) { cnt[t] = 0; cur[t] = 0; }
        __syncthreads();
        for (int i = t; i < R; i += TPB) {
            const int b = (int)rois[i * 5];
            atomicAdd(&cnt[b], 1);
        }
        __syncthreads();
        if (t == 0) { base[0] = 0; base[1] = cnt[0]; }
        __syncthreads();
        for (int i = t; i < R; i += TPB) {
            const int b = (int)rois[i * 5];
            const int pos = atomicAdd(&cur[b], 1);
            g_sorted[base[b] + pos] = i;
        }
        __threadfence();
        __syncthreads();
        if (t == 0) atomicExch(&g_sync[2], 1);
        return;
    }

    if (bid <= TB_PER_BATCH) {
        do_transpose(feats, 0, bid - 1, t, reinterpret_cast<float*>(smem_raw));
        return;
    }

    int slot;
    if (bid <= TB_PER_BATCH + ILV) {
        const int j = bid - TB_PER_BATCH - 1;      // 0..5899
        const int grp = j / 59, rem = j - grp * 59;
        if (rem < 24) {   // T1 block
            do_transpose(feats, 1, grp * 24 + rem, t, reinterpret_cast<float*>(smem_raw));
            return;
        }
        slot = grp * 35 + (rem - 24);              // 0..3499
    } else {
        slot = 3500 + (bid - (TB_PER_BATCH + ILV + 1));   // 3500..6999
    }

    // ---------------- gather role ----------------
    unsigned int* sout = reinterpret_cast<unsigned int*>(smem_raw);
    const int cg   = t & 31;
    const int lane = t >> 5;   // 0..13 = ow

    // wait for sort, fetch ROI index (written in-kernel -> coherent read)
    __shared__ int sh_r;
    if (t == 0) {
        while (((volatile int*)g_sync)[2] == 0) __nanosleep(100);
        sh_r = ((volatile int*)g_sorted)[slot / 7];
    }
    __syncthreads();
    const int r   = sh_r;
    const int oh0 = (slot % 7) * 2;

    const float bf = __ldg(&rois[r * 5 + 0]);
    const float x1 = __ldg(&rois[r * 5 + 1]);
    const float y1 = __ldg(&rois[r * 5 + 2]);
    const float x2 = __ldg(&rois[r * 5 + 3]);
    const float y2 = __ldg(&rois[r * 5 + 4]);
    const int  b   = (int)bf;

    // wait until this batch's features are transposed
    if (t == 0) {
        while (((volatile int*)g_sync)[b] < TB_PER_BATCH) __nanosleep(200);
        __threadfence();
    }
    __syncthreads();

    const uint4* f4 = reinterpret_cast<const uint4*>(g_feat) + (size_t)b * HW * 32;

    const float gx  = ((float)lane + 0.5f) * (1.0f / OW);
    const float fx  = (x1 + gx * (x2 - x1)) * SCALE - 0.5f;
    const float x0f = floorf(fx);
    const float lx  = fx - x0f;
    const int   xi0 = (int)x0f;
    const int   xi1 = xi0 + 1;
    const float wx0 = (1.0f - lx) * ((xi0 >= 0 && xi0 < W) ? 1.0f : 0.0f);
    const float wx1 = lx * ((xi1 >= 0 && xi1 < W) ? 1.0f : 0.0f);
    const int   x0c = min(max(xi0, 0), W - 1);
    const int   x1c = min(max(xi1, 0), W - 1);

    #pragma unroll
    for (int k = 0; k < 2; k++) {
        const int s  = lane + k * 14;
        const int oh = oh0 + k;

        const float gy  = ((float)oh + 0.5f) * (1.0f / OH);
        const float fy  = (y1 + gy * (y2 - y1)) * SCALE - 0.5f;
        const float y0f = floorf(fy);
        const float ly  = fy - y0f;
        const int   yi0 = (int)y0f;
        const int   yi1 = yi0 + 1;
        const float wy0 = (1.0f - ly) * ((yi0 >= 0 && yi0 < H) ? 1.0f : 0.0f);
        const float wy1 = ly * ((yi1 >= 0 && yi1 < H) ? 1.0f : 0.0f);
        const int   y0c = min(max(yi0, 0), H - 1);
        const int   y1c = min(max(yi1, 0), H - 1);

        const float w00 = wy0 * wx0;
        const float w01 = wy0 * wx1;
        const float w10 = wy1 * wx0;
        const float w11 = wy1 * wx1;

        // Coherent (L2) front-batched corner loads (MLP=4)
        const uint4 u00 = __ldcg(&f4[(size_t)(y0c * W + x0c) * 32 + cg]);
        const uint4 u01 = __ldcg(&f4[(size_t)(y0c * W + x1c) * 32 + cg]);
        const uint4 u10 = __ldcg(&f4[(size_t)(y1c * W + x0c) * 32 + cg]);
        const uint4 u11 = __ldcg(&f4[(size_t)(y1c * W + x1c) * 32 + cg]);

        float o0, o1, o2, o3, o4, o5, o6, o7;
        #define BLEND(CMP, OA, OB)                                                        \
            {                                                                             \
                const float2 a = __half22float2(*reinterpret_cast<const __half2*>(&u00.CMP)); \
                const float2 bq = __half22float2(*reinterpret_cast<const __half2*>(&u01.CMP)); \
                const float2 c = __half22float2(*reinterpret_cast<const __half2*>(&u10.CMP)); \
                const float2 dq = __half22float2(*reinterpret_cast<const __half2*>(&u11.CMP)); \
                OA = fmaf(w00, a.x, fmaf(w01, bq.x, fmaf(w10, c.x, w11 * dq.x)));         \
                OB = fmaf(w00, a.y, fmaf(w01, bq.y, fmaf(w10, c.y, w11 * dq.y)));         \
            }
        BLEND(x, o0, o1)
        BLEND(y, o2, o3)
        BLEND(z, o4, o5)
        BLEND(w, o6, o7)
        #undef BLEND

        const __half2 h01 = __floats2half2_rn(o0, o1);
        const __half2 h23 = __floats2half2_rn(o2, o3);
        const __half2 h45 = __floats2half2_rn(o4, o5);
        const __half2 h67 = __floats2half2_rn(o6, o7);
        const int E = s >> 2;
        uint4 pk;
        pk.x = *reinterpret_cast<const unsigned int*>(&h01);
        pk.y = *reinterpret_cast<const unsigned int*>(&h23);
        pk.z = *reinterpret_cast<const unsigned int*>(&h45);
        pk.w = *reinterpret_cast<const unsigned int*>(&h67);
        *reinterpret_cast<uint4*>(&sout[s * RW + 4 * (cg ^ E)]) = pk;
    }
    __syncthreads();

    // Writeback: 448 units = 64 channel-quads x 7 sample-quads; 1 per thread.
    {
        const int q  = t / 7;
        const int jq = t - q * 7;
        const int jj0 = jq * 4;
        const int Wd  = 4 * ((q >> 1) ^ jq) + 2 * (q & 1);

        float2 fa[4], fb[4];
        #pragma unroll
        for (int i = 0; i < 4; i++) {
            const uint2 v = *reinterpret_cast<const uint2*>(&sout[(jj0 + i) * RW + Wd]);
            fa[i] = __half22float2(*reinterpret_cast<const __half2*>(&v.x));
            fb[i] = __half22float2(*reinterpret_cast<const __half2*>(&v.y));
        }

        float* ob = out + (size_t)r * C * (OH * OW)
                        + (size_t)(q * 4) * (OH * OW) + oh0 * OW + jj0;
        __stcs((float4*)(ob),                 make_float4(fa[0].x, fa[1].x, fa[2].x, fa[3].x));
        __stcs((float4*)(ob +     (OH * OW)), make_float4(fa[0].y, fa[1].y, fa[2].y, fa[3].y));
        __stcs((float4*)(ob + 2 * (OH * OW)), make_float4(fb[0].x, fb[1].x, fb[2].x, fb[3].x));
        __stcs((float4*)(ob + 3 * (OH * OW)), make_float4(fb[0].y, fb[1].y, fb[2].y, fb[3].y));
    }
}

// ---------------------------------------------------------------------------
extern "C" void kernel_launch(void* const* d_in, const int* in_sizes, int n_in,
                              void* d_out, int out_size) {
    const float* features = (const float*)d_in[0];
    const float* rois     = (const float*)d_in[1];
    if (n_in >= 2 && in_sizes[0] == R * 5) {
        features = (const float*)d_in[1];
        rois     = (const float*)d_in[0];
    }
    float* out = (float*)d_out;

    init_ctr_kernel<<<1, 32>>>();
    fused_kernel<<<GRID_TOTAL, TPB>>>(features, rois, out);
}

// round 15
// speedup vs baseline: 1.0733x; 1.0733x over previous
#include <cuda_runtime.h>
#include <cuda_fp16.h>

// Problem constants
#define B  2
#define C  256
#define H  200
#define W  336
#define R  1000
#define OH 14
#define OW 14
#define HW (H * W)           // 67200
#define SCALE 0.25f

// NHWC features in fp16: 2*67200*256*2B = 68.8 MB
__device__ static __half g_feat[(size_t)B * HW * C];

// ---------------------------------------------------------------------------
// Kernel 1: NCHW fp32 -> NHWC fp16 transpose (4x4 register micro-transpose,
// XOR-swizzled smem). Source reads streamed (__ldcs): single use.
// ---------------------------------------------------------------------------
#define TSTRIDE 68
__global__ __launch_bounds__(256) void transpose_kernel(const float* __restrict__ src) {
    __shared__ float tileT[64 * TSTRIDE];

    const int batch = blockIdx.z;
    const int p0 = blockIdx.x * 64;
    const int c0 = blockIdx.y * 64;
    const float* s = src + (size_t)batch * C * HW;
    __half*      d = g_feat + (size_t)batch * HW * C;

    {
        const int tx = threadIdx.x & 15;
        const int ty = threadIdx.x >> 4;
        const float* rb = s + (size_t)(c0 + ty * 4) * HW + p0 + tx * 4;
        const float4 v0 = __ldcs((const float4*)(rb));
        const float4 v1 = __ldcs((const float4*)(rb + HW));
        const float4 v2 = __ldcs((const float4*)(rb + 2 * (size_t)HW));
        const float4 v3 = __ldcs((const float4*)(rb + 3 * (size_t)HW));

        float* wb = &tileT[(4 * tx) * TSTRIDE + 4 * ((ty ^ tx) & 15)];
        *(float4*)(wb + 0 * TSTRIDE) = make_float4(v0.x, v1.x, v2.x, v3.x);
        *(float4*)(wb + 1 * TSTRIDE) = make_float4(v0.y, v1.y, v2.y, v3.y);
        *(float4*)(wb + 2 * TSTRIDE) = make_float4(v0.z, v1.z, v2.z, v3.z);
        *(float4*)(wb + 3 * TSTRIDE) = make_float4(v0.w, v1.w, v2.w, v3.w);
    }
    __syncthreads();

    {
        const int c4 = threadIdx.x & 15;
        const int pr = threadIdx.x >> 4;
        #pragma unroll
        for (int k = 0; k < 4; k++) {
            const int p = pr + k * 16;
            const float4 w = *(const float4*)&tileT[p * TSTRIDE + 4 * ((c4 ^ (p >> 2)) & 15)];
            const __half2 h0 = __floats2half2_rn(w.x, w.y);
            const __half2 h1 = __floats2half2_rn(w.z, w.w);
            uint2 u;
            u.x = *reinterpret_cast<const unsigned int*>(&h0);
            u.y = *reinterpret_cast<const unsigned int*>(&h1);
            *reinterpret_cast<uint2*>(d + (size_t)(p0 + p) * C + c0 + c4 * 4) = u;
        }
    }
}

// ---------------------------------------------------------------------------
// Kernel 2: ROI-align gather. Block = (roi PAIR, oh-pair): grid 3500,
// 448 threads = 32 channel-groups (8ch, uint4) x 14 lanes.
// Each thread: 4 samples (2 rois x 2 oh rows) -> per-block overheads
// (headers, barrier, writeback setup) amortized 2x vs one-roi blocks.
// fp16 staging, layout per r11 (conflict-free STS.128 / LDS.64).
// ---------------------------------------------------------------------------
#define RW 132   // staging row stride in 32-bit words

__global__ __launch_bounds__(448, 4) void roi_gather_kernel(
    const float* __restrict__ rois, float* __restrict__ out)
{
    const int blk  = blockIdx.x;
    const int pr   = blk / 7;                 // roi pair 0..499
    const int oh0  = (blk - pr * 7) * 2;
    const int r0   = pr * 2;
    const int t    = threadIdx.x;
    const int cg   = t & 31;    // channel group: channels 8cg..8cg+7
    const int lane = t >> 5;    // 0..13 = ow

    __shared__ unsigned int sout[2 * 28 * RW];   // 29.6 KB (fp16 staging)

    // prefetch both roi headers
    const float bf0 = __ldg(&rois[r0 * 5 + 0]);
    const float ax1 = __ldg(&rois[r0 * 5 + 1]);
    const float ay1 = __ldg(&rois[r0 * 5 + 2]);
    const float ax2 = __ldg(&rois[r0 * 5 + 3]);
    const float ay2 = __ldg(&rois[r0 * 5 + 4]);
    const float bf1 = __ldg(&rois[r0 * 5 + 5]);
    const float bx1 = __ldg(&rois[r0 * 5 + 6]);
    const float by1 = __ldg(&rois[r0 * 5 + 7]);
    const float bx2 = __ldg(&rois[r0 * 5 + 8]);
    const float by2 = __ldg(&rois[r0 * 5 + 9]);

    #pragma unroll
    for (int ri = 0; ri < 2; ri++) {
        const float x1 = ri ? bx1 : ax1;
        const float y1 = ri ? by1 : ay1;
        const float x2 = ri ? bx2 : ax2;
        const float y2 = ri ? by2 : ay2;
        const int   b  = (int)(ri ? bf1 : bf0);

        const uint4* f4 = reinterpret_cast<const uint4*>(g_feat) + (size_t)b * HW * 32;

        // x-geometry shared by both oh rows (same ow)
        const float gx  = ((float)lane + 0.5f) * (1.0f / OW);
        const float fx  = (x1 + gx * (x2 - x1)) * SCALE - 0.5f;
        const float x0f = floorf(fx);
        const float lx  = fx - x0f;
        const int   xi0 = (int)x0f;
        const int   xi1 = xi0 + 1;
        const float wx0 = (1.0f - lx) * ((xi0 >= 0 && xi0 < W) ? 1.0f : 0.0f);
        const float wx1 = lx * ((xi1 >= 0 && xi1 < W) ? 1.0f : 0.0f);
        const int   x0c = min(max(xi0, 0), W - 1);
        const int   x1c = min(max(xi1, 0), W - 1);

        #pragma unroll
        for (int k = 0; k < 2; k++) {
            const int s  = lane + k * 14;
            const int oh = oh0 + k;

            const float gy  = ((float)oh + 0.5f) * (1.0f / OH);
            const float fy  = (y1 + gy * (y2 - y1)) * SCALE - 0.5f;
            const float y0f = floorf(fy);
            const float ly  = fy - y0f;
            const int   yi0 = (int)y0f;
            const int   yi1 = yi0 + 1;
            const float wy0 = (1.0f - ly) * ((yi0 >= 0 && yi0 < H) ? 1.0f : 0.0f);
            const float wy1 = ly * ((yi1 >= 0 && yi1 < H) ? 1.0f : 0.0f);
            const int   y0c = min(max(yi0, 0), H - 1);
            const int   y1c = min(max(yi1, 0), H - 1);

            const float w00 = wy0 * wx0;
            const float w01 = wy0 * wx1;
            const float w10 = wy1 * wx0;
            const float w11 = wy1 * wx1;

            // Unconditional, front-batched corner loads (MLP=4)
            const uint4 u00 = __ldg(&f4[(size_t)(y0c * W + x0c) * 32 + cg]);
            const uint4 u01 = __ldg(&f4[(size_t)(y0c * W + x1c) * 32 + cg]);
            const uint4 u10 = __ldg(&f4[(size_t)(y1c * W + x0c) * 32 + cg]);
            const uint4 u11 = __ldg(&f4[(size_t)(y1c * W + x1c) * 32 + cg]);

            float o0, o1, o2, o3, o4, o5, o6, o7;
            #define BLEND(CMP, OA, OB)                                                        \
                {                                                                             \
                    const float2 a = __half22float2(*reinterpret_cast<const __half2*>(&u00.CMP)); \
                    const float2 bq = __half22float2(*reinterpret_cast<const __half2*>(&u01.CMP)); \
                    const float2 c = __half22float2(*reinterpret_cast<const __half2*>(&u10.CMP)); \
                    const float2 dq = __half22float2(*reinterpret_cast<const __half2*>(&u11.CMP)); \
                    OA = fmaf(w00, a.x, fmaf(w01, bq.x, fmaf(w10, c.x, w11 * dq.x)));         \
                    OB = fmaf(w00, a.y, fmaf(w01, bq.y, fmaf(w10, c.y, w11 * dq.y)));         \
                }
            BLEND(x, o0, o1)
            BLEND(y, o2, o3)
            BLEND(z, o4, o5)
            BLEND(w, o6, o7)
            #undef BLEND

            // Pack to fp16 and stage: one STS.128 per sample.
            const __half2 h01 = __floats2half2_rn(o0, o1);
            const __half2 h23 = __floats2half2_rn(o2, o3);
            const __half2 h45 = __floats2half2_rn(o4, o5);
            const __half2 h67 = __floats2half2_rn(o6, o7);
            const int E = s >> 2;
            uint4 pk;
            pk.x = *reinterpret_cast<const unsigned int*>(&h01);
            pk.y = *reinterpret_cast<const unsigned int*>(&h23);
            pk.z = *reinterpret_cast<const unsigned int*>(&h45);
            pk.w = *reinterpret_cast<const unsigned int*>(&h67);
            *reinterpret_cast<uint4*>(&sout[(ri * 28 + s) * RW + 4 * (cg ^ E)]) = pk;
        }
    }
    __syncthreads();

    // Writeback: 896 units = 2 rois x 64 channel-quads x 7 sample-quads;
    // 2 per thread (t and t+448).
    #pragma unroll
    for (int uu = 0; uu < 2; uu++) {
        const int unit = t + uu * 448;
        const int ri   = unit >> 8 >= 0 ? unit / 448 : 0;   // 0 or 1
        const int loc  = unit - ri * 448;
        const int q    = loc / 7;            // channel quad: channels 4q..4q+3
        const int jq   = loc - q * 7;        // sample quad:  samples 4jq..4jq+3
        const int jj0  = jq * 4;
        const int Wd   = 4 * ((q >> 1) ^ jq) + 2 * (q & 1);
        const unsigned int* sbase = &sout[(ri * 28) * RW];

        float2 fa[4], fb[4];
        #pragma unroll
        for (int i = 0; i < 4; i++) {
            const uint2 v = *reinterpret_cast<const uint2*>(&sbase[(jj0 + i) * RW + Wd]);
            fa[i] = __half22float2(*reinterpret_cast<const __half2*>(&v.x)); // ch 4q,4q+1
            fb[i] = __half22float2(*reinterpret_cast<const __half2*>(&v.y)); // ch 4q+2,4q+3
        }

        float* ob = out + (size_t)(r0 + ri) * C * (OH * OW)
                        + (size_t)(q * 4) * (OH * OW) + oh0 * OW + jj0;
        __stcs((float4*)(ob),                 make_float4(fa[0].x, fa[1].x, fa[2].x, fa[3].x));
        __stcs((float4*)(ob +     (OH * OW)), make_float4(fa[0].y, fa[1].y, fa[2].y, fa[3].y));
        __stcs((float4*)(ob + 2 * (OH * OW)), make_float4(fb[0].x, fb[1].x, fb[2].x, fb[3].x));
        __stcs((float4*)(ob + 3 * (OH * OW)), make_float4(fb[0].y, fb[1].y, fb[2].y, fb[3].y));
    }
}

// ---------------------------------------------------------------------------
extern "C" void kernel_launch(void* const* d_in, const int* in_sizes, int n_in,
                              void* d_out, int out_size) {
    const float* features = (const float*)d_in[0];
    const float* rois     = (const float*)d_in[1];
    if (n_in >= 2 && in_sizes[0] == R * 5) {
        features = (const float*)d_in[1];
        rois     = (const float*)d_in[0];
    }
    float* out = (float*)d_out;

    dim3 tgrid(HW / 64, C / 64, B);   // (1050, 4, 2)
    transpose_kernel<<<tgrid, 256>>>(features);

    roi_gather_kernel<<<(R / 2) * 7, 448>>>(rois, out);
}